// round 9
// baseline (speedup 1.0000x reference)
#include <cuda_runtime.h>

// Depthwise 5x5 blur, x: (32,128,128,128) fp32 = 4096 images of 128x128.
// w[dy][dx] = exp(-((dy^2+dx^2)^2)/(2*exp(log_ls))), normalized. Fully symmetric:
// 6 distinct weights (s = dy^2+dx^2 in {0,1,2,4,5,8}).
// R6 structure + persistent grid-stride over images (grid = 148*4, weights
// computed once per block) + first-touch-assign accumulators (no init/reset).

#define RAD 2
#define WID 128
#define STRIP 16
#define NROWS (STRIP + 4)
#define NIMG  4096
#define GRID  592          // 148 SMs * 4 resident blocks

typedef unsigned long long u64;

__device__ __forceinline__ u64 pk(float lo, float hi) {
    u64 r; asm("mov.b64 %0, {%1, %2};" : "=l"(r) : "f"(lo), "f"(hi)); return r;
}
__device__ __forceinline__ u64 pk1(float v) {
    u64 r; asm("mov.b64 %0, {%1, %1};" : "=l"(r) : "f"(v)); return r;
}
__device__ __forceinline__ u64 add2(u64 a, u64 b) {
    u64 r; asm("add.rn.f32x2 %0, %1, %2;" : "=l"(r) : "l"(a), "l"(b)); return r;
}
__device__ __forceinline__ u64 mul2(u64 a, u64 b) {
    u64 r; asm("mul.rn.f32x2 %0, %1, %2;" : "=l"(r) : "l"(a), "l"(b)); return r;
}
__device__ __forceinline__ void fma2(u64& d, u64 a, u64 b) {
    asm("fma.rn.f32x2 %0, %1, %2, %0;" : "+l"(d) : "l"(a), "l"(b));
}
__device__ __forceinline__ float2 unpk(u64 a) {
    float2 v; asm("mov.b64 {%0, %1}, %2;" : "=f"(v.x), "=f"(v.y) : "l"(a)); return v;
}

// Thread layout: lane = tid&31 -> 4 output cols (c=lane*4);
// strip = tid>>5 (0..7) -> 16 output rows. One image per block-iteration.
// Persistent: each block strides over images. No shared memory.
__global__ void __launch_bounds__(256, 4)
blur_main_kernel(const float* __restrict__ x, float* __restrict__ out,
                 const float* __restrict__ logls) {
    const int tid   = threadIdx.x;
    const int lane  = tid & 31;
    const int strip = tid >> 5;
    const int c     = lane * 4;
    const int row0  = strip * STRIP;

    // ---- Per-block weight table (once per block, not per image) ----
    const float inv2ls = 0.5f * expf(-logls[0]);   // 1/(2*exp(logls))
    const float e1 = expf(-1.0f  * inv2ls);
    const float e2 = expf(-4.0f  * inv2ls);
    const float e4 = expf(-16.0f * inv2ls);
    const float e5 = expf(-25.0f * inv2ls);
    const float e8 = expf(-64.0f * inv2ls);
    const float inv = 1.0f / (1.0f + 4.0f * (e1 + e2 + e4 + e8) + 8.0f * e5);
    u64 wp[6];
    wp[0] = pk1(e8 * inv);   // s=8  (|dy|=2,|dx|=2)
    wp[1] = pk1(e5 * inv);   // s=5  (2,1)/(1,2)
    wp[2] = pk1(e4 * inv);   // s=4  (2,0)/(0,2)
    wp[3] = pk1(e2 * inv);   // s=2  (1,1)
    wp[4] = pk1(e1 * inv);   // s=1  (1,0)/(0,1)
    wp[5] = pk1(inv);        // s=0  (0,0)

    const bool has_l = (lane > 0);
    const bool has_h = (lane < 31);

    for (int img = blockIdx.x; img < NIMG; img += GRID) {
        const float* rowp = x + (size_t)img * (WID * WID) + (row0 - RAD) * WID + c;
        float*       outp = out + (size_t)img * (WID * WID) + row0 * WID + c;

        // Triple-buffered row registers (prefetch distance 2).
        float4 a[3];
        #pragma unroll
        for (int pr = 0; pr < 2; pr++) {
            const int gr = row0 + pr - RAD;
            a[pr] = make_float4(0.f, 0.f, 0.f, 0.f);
            if ((unsigned)gr < (unsigned)WID)
                a[pr] = *(const float4*)(rowp);
            rowp += WID;
        }

        // Ring of 5 accumulator pairs; first touch (d==4) assigns, so no init.
        u64 acc0[5], acc1[5];

        #pragma unroll
        for (int r = 0; r < NROWS; r++) {
            // Prefetch row r+2.
            if (r + 2 < NROWS) {
                const int gr = row0 + (r + 2) - RAD;
                const int b  = (r + 2) % 3;
                a[b] = make_float4(0.f, 0.f, 0.f, 0.f);
                if ((unsigned)gr < (unsigned)WID)
                    a[b] = *(const float4*)(rowp);
                rowp += WID;
            }

            const float4 av = a[r % 3];

            // Halo via warp shuffle: x[-2],x[-1] from lane-1; x[4],x[5] from lane+1.
            float slx = __shfl_up_sync(0xffffffffu, av.z, 1);
            float sly = __shfl_up_sync(0xffffffffu, av.w, 1);
            float shx = __shfl_down_sync(0xffffffffu, av.x, 1);
            float shy = __shfl_down_sync(0xffffffffu, av.y, 1);
            const float lx = has_l ? slx : 0.f;
            const float ly = has_l ? sly : 0.f;
            const float hx = has_h ? shx : 0.f;
            const float hy = has_h ? shy : 0.f;

            // Horizontal pair-sums for cols (c,c+1) and (c+2,c+3).
            // x[-2..5] = lx,ly, av.x,av.y,av.z,av.w, hx,hy
            u64 p01 = pk(av.x, av.y);
            u64 p23 = pk(av.z, av.w);
            u64 t1a = add2(pk(lx, ly), p23);                  // (x-2+x2, x-1+x3)
            u64 t2a = add2(pk(ly, av.x), pk(av.y, av.z));     // (x-1+x1, x0+x2)
            u64 t1b = add2(p01, pk(hx, hy));                  // (x0+x4,  x1+x5)
            u64 t2b = add2(pk(av.y, av.z), pk(av.w, hx));     // (x1+x3,  x2+x4)

            #pragma unroll
            for (int d = 0; d < 5; d++) {
                const int o = r - 4 + d;                      // receiving output row
                if (o < 0 || o >= STRIP) continue;            // constant-folded
                const int k = 2 - ((d < 2) ? (2 - d) : (d - 2));  // row class 0,1,2,1,0
                const int i0 = (k == 0) ? 0 : (k == 1 ? 1 : 2);   // |dx|=2 weight
                const int i1 = (k == 0) ? 1 : (k == 1 ? 3 : 4);   // |dx|=1 weight
                const int i2 = (k == 0) ? 2 : (k == 1 ? 4 : 5);   // dx=0  weight
                const int s = o % 5;
                if (d == 4) {                                 // first touch: assign
                    acc0[s] = mul2(wp[i0], t1a);
                    acc1[s] = mul2(wp[i0], t1b);
                } else {
                    fma2(acc0[s], wp[i0], t1a);
                    fma2(acc1[s], wp[i0], t1b);
                }
                fma2(acc0[s], wp[i1], t2a);
                fma2(acc0[s], wp[i2], p01);
                fma2(acc1[s], wp[i1], t2b);
                fma2(acc1[s], wp[i2], p23);
            }

            const int o = r - 4;                              // row completed now
            if (o >= 0) {                                     // constant-folded
                const int s = o % 5;
                float2 lo = unpk(acc0[s]);
                float2 hi = unpk(acc1[s]);
                __stcs((float4*)outp, make_float4(lo.x, lo.y, hi.x, hi.y));
                outp += WID;
            }
        }
    }
}

extern "C" void kernel_launch(void* const* d_in, const int* in_sizes, int n_in,
                              void* d_out, int out_size) {
    const float* x     = (const float*)d_in[0];
    const float* logls = (const float*)d_in[1];
    float* out = (float*)d_out;

    blur_main_kernel<<<GRID, 256>>>(x, out, logls);
}

// round 10
// speedup vs baseline: 1.1496x; 1.1496x over previous
#include <cuda_runtime.h>

// Depthwise 5x5 blur, x: (32,128,128,128) fp32 = 4096 images of 128x128.
// w[dy][dx] = exp(-((dy^2+dx^2)^2)/(2*exp(log_ls))), normalized. Fully symmetric:
// 6 distinct exponentials (s = dy^2+dx^2 in {0,1,2,4,5,8}), 3x3 distinct weights.
// R6 structure (best measured): one block per image, 8 strips x 16 rows,
// shuffle halos, packed fma.rn.f32x2, triple-buffered prefetch, grid=4096.
// Plus: first-touch-assign accumulators (no ring init / reset movs).

#define RAD 2
#define WID 128
#define STRIP 16
#define NROWS (STRIP + 4)

typedef unsigned long long u64;

__device__ __forceinline__ u64 pk(float lo, float hi) {
    u64 r; asm("mov.b64 %0, {%1, %2};" : "=l"(r) : "f"(lo), "f"(hi)); return r;
}
__device__ __forceinline__ u64 pk1(float v) {
    u64 r; asm("mov.b64 %0, {%1, %1};" : "=l"(r) : "f"(v)); return r;
}
__device__ __forceinline__ u64 add2(u64 a, u64 b) {
    u64 r; asm("add.rn.f32x2 %0, %1, %2;" : "=l"(r) : "l"(a), "l"(b)); return r;
}
__device__ __forceinline__ u64 mul2(u64 a, u64 b) {
    u64 r; asm("mul.rn.f32x2 %0, %1, %2;" : "=l"(r) : "l"(a), "l"(b)); return r;
}
__device__ __forceinline__ void fma2(u64& d, u64 a, u64 b) {
    asm("fma.rn.f32x2 %0, %1, %2, %0;" : "+l"(d) : "l"(a), "l"(b));
}
__device__ __forceinline__ float2 unpk(u64 a) {
    float2 v; asm("mov.b64 {%0, %1}, %2;" : "=f"(v.x), "=f"(v.y) : "l"(a)); return v;
}

// Thread layout: lane = tid&31 -> 4 output cols (c=lane*4);
// strip = tid>>5 (0..7) -> 16 output rows. One image per 256-thread block.
// Grid = 4096 blocks. No shared memory.
__global__ void __launch_bounds__(256, 4)
blur_main_kernel(const float* __restrict__ x, float* __restrict__ out,
                 const float* __restrict__ logls) {
    const int tid   = threadIdx.x;
    const int lane  = tid & 31;
    const int strip = tid >> 5;
    const int img   = blockIdx.x;
    const int c     = lane * 4;
    const int row0  = strip * STRIP;

    // ---- Per-thread weight table (5 expf, overlapped with first prefetch) ----
    const float inv2ls = 0.5f * expf(-logls[0]);   // 1/(2*exp(logls))
    const float e1 = expf(-1.0f  * inv2ls);
    const float e2 = expf(-4.0f  * inv2ls);
    const float e4 = expf(-16.0f * inv2ls);
    const float e5 = expf(-25.0f * inv2ls);
    const float e8 = expf(-64.0f * inv2ls);
    const float inv = 1.0f / (1.0f + 4.0f * (e1 + e2 + e4 + e8) + 8.0f * e5);
    // wp[k*3+j]: k = row class (|dy|=2-k), j = col class (|dx|=2-j)
    u64 wp[9];
    wp[0] = pk1(e8 * inv); wp[1] = pk1(e5 * inv); wp[2] = pk1(e4 * inv);
    wp[3] = wp[1];         wp[4] = pk1(e2 * inv); wp[5] = pk1(e1 * inv);
    wp[6] = wp[2];         wp[7] = wp[5];         wp[8] = pk1(inv);

    const float* rowp = x + (size_t)img * (WID * WID) + (row0 - RAD) * WID + c;
    float*       outp = out + (size_t)img * (WID * WID) + row0 * WID + c;

    const bool has_l = (lane > 0);
    const bool has_h = (lane < 31);

    // Triple-buffered row registers (prefetch distance 2).
    float4 a[3];
    #pragma unroll
    for (int pr = 0; pr < 2; pr++) {
        const int gr = row0 + pr - RAD;
        a[pr] = make_float4(0.f, 0.f, 0.f, 0.f);
        if ((unsigned)gr < (unsigned)WID)
            a[pr] = *(const float4*)(rowp);
        rowp += WID;
    }

    // Ring of 5 accumulator pairs; first touch (d==4) assigns -> no init/reset.
    u64 acc0[5], acc1[5];

    #pragma unroll
    for (int r = 0; r < NROWS; r++) {
        // Prefetch row r+2.
        if (r + 2 < NROWS) {
            const int gr = row0 + (r + 2) - RAD;
            const int b  = (r + 2) % 3;
            a[b] = make_float4(0.f, 0.f, 0.f, 0.f);
            if ((unsigned)gr < (unsigned)WID)
                a[b] = *(const float4*)(rowp);
            rowp += WID;
        }

        const float4 av = a[r % 3];

        // Halo via warp shuffle: x[-2],x[-1] from lane-1; x[4],x[5] from lane+1.
        float slx = __shfl_up_sync(0xffffffffu, av.z, 1);
        float sly = __shfl_up_sync(0xffffffffu, av.w, 1);
        float shx = __shfl_down_sync(0xffffffffu, av.x, 1);
        float shy = __shfl_down_sync(0xffffffffu, av.y, 1);
        const float lx = has_l ? slx : 0.f;
        const float ly = has_l ? sly : 0.f;
        const float hx = has_h ? shx : 0.f;
        const float hy = has_h ? shy : 0.f;

        // Horizontal pair-sums for cols (c,c+1) and (c+2,c+3).
        // x[-2..5] = lx,ly, av.x,av.y,av.z,av.w, hx,hy
        u64 p01 = pk(av.x, av.y);
        u64 p23 = pk(av.z, av.w);
        u64 t1a = add2(pk(lx, ly), p23);                  // (x-2+x2, x-1+x3)
        u64 t2a = add2(pk(ly, av.x), pk(av.y, av.z));     // (x-1+x1, x0+x2)
        u64 t1b = add2(p01, pk(hx, hy));                  // (x0+x4,  x1+x5)
        u64 t2b = add2(pk(av.y, av.z), pk(av.w, hx));     // (x1+x3,  x2+x4)

        #pragma unroll
        for (int d = 0; d < 5; d++) {
            const int o = r - 4 + d;                      // receiving output row
            if (o < 0 || o >= STRIP) continue;            // constant-folded
            const int k = 2 - ((d < 2) ? (2 - d) : (d - 2));  // 0,1,2,1,0
            const int s = o % 5;
            if (d == 4) {                                 // first touch: assign
                acc0[s] = mul2(wp[k * 3 + 0], t1a);
                acc1[s] = mul2(wp[k * 3 + 0], t1b);
            } else {
                fma2(acc0[s], wp[k * 3 + 0], t1a);
                fma2(acc1[s], wp[k * 3 + 0], t1b);
            }
            fma2(acc0[s], wp[k * 3 + 1], t2a);
            fma2(acc0[s], wp[k * 3 + 2], p01);
            fma2(acc1[s], wp[k * 3 + 1], t2b);
            fma2(acc1[s], wp[k * 3 + 2], p23);
        }

        const int o = r - 4;                              // row completed now
        if (o >= 0) {                                     // constant-folded
            const int s = o % 5;
            float2 lo = unpk(acc0[s]);
            float2 hi = unpk(acc1[s]);
            __stcs((float4*)outp, make_float4(lo.x, lo.y, hi.x, hi.y));
            outp += WID;
        }
    }
}

extern "C" void kernel_launch(void* const* d_in, const int* in_sizes, int n_in,
                              void* d_out, int out_size) {
    const float* x     = (const float*)d_in[0];
    const float* logls = (const float*)d_in[1];
    float* out = (float*)d_out;

    blur_main_kernel<<<4096, 256>>>(x, out, logls);
}

// round 11
// speedup vs baseline: 1.1584x; 1.0076x over previous
#include <cuda_runtime.h>

// Depthwise 5x5 blur, x: (32,128,128,128) fp32 = 4096 images of 128x128.
// w[dy][dx] = exp(-((dy^2+dx^2)^2)/(2*exp(log_ls))), normalized. Fully symmetric.
// R10 structure (best measured): one block per image, 8 strips x 16 rows,
// shuffle halos, packed fma.rn.f32x2, triple-buffered prefetch, grid=4096,
// first-touch-assign accumulators.
// Plus: warp-uniform guard specialization — only strips 0 and 7 carry row
// bounds checks; interior warps run a branch-free body.

#define RAD 2
#define WID 128
#define STRIP 16
#define NROWS (STRIP + 4)

typedef unsigned long long u64;

__device__ __forceinline__ u64 pk(float lo, float hi) {
    u64 r; asm("mov.b64 %0, {%1, %2};" : "=l"(r) : "f"(lo), "f"(hi)); return r;
}
__device__ __forceinline__ u64 pk1(float v) {
    u64 r; asm("mov.b64 %0, {%1, %1};" : "=l"(r) : "f"(v)); return r;
}
__device__ __forceinline__ u64 add2(u64 a, u64 b) {
    u64 r; asm("add.rn.f32x2 %0, %1, %2;" : "=l"(r) : "l"(a), "l"(b)); return r;
}
__device__ __forceinline__ u64 mul2(u64 a, u64 b) {
    u64 r; asm("mul.rn.f32x2 %0, %1, %2;" : "=l"(r) : "l"(a), "l"(b)); return r;
}
__device__ __forceinline__ void fma2(u64& d, u64 a, u64 b) {
    asm("fma.rn.f32x2 %0, %1, %2, %0;" : "+l"(d) : "l"(a), "l"(b));
}
__device__ __forceinline__ float2 unpk(u64 a) {
    float2 v; asm("mov.b64 {%0, %1}, %2;" : "=f"(v.x), "=f"(v.y) : "l"(a)); return v;
}

// wp[k*3+j]: k = row class (|dy|=2-k), j = col class (|dx|=2-j).
template <bool GUARD>
__device__ __forceinline__ void blur_strip(
    const float* __restrict__ rowp, float* __restrict__ outp,
    const u64* __restrict__ wp, bool has_l, bool has_h, int row0)
{
    // Triple-buffered row registers (prefetch distance 2).
    float4 a[3];
    #pragma unroll
    for (int pr = 0; pr < 2; pr++) {
        if (GUARD) {
            const int gr = row0 + pr - RAD;
            a[pr] = make_float4(0.f, 0.f, 0.f, 0.f);
            if ((unsigned)gr < (unsigned)WID)
                a[pr] = *(const float4*)(rowp);
        } else {
            a[pr] = *(const float4*)(rowp);
        }
        rowp += WID;
    }

    // Ring of 5 accumulator pairs; first touch (d==4) assigns -> no init/reset.
    u64 acc0[5], acc1[5];

    #pragma unroll
    for (int r = 0; r < NROWS; r++) {
        // Prefetch row r+2.
        if (r + 2 < NROWS) {
            const int b = (r + 2) % 3;
            if (GUARD) {
                const int gr = row0 + (r + 2) - RAD;
                a[b] = make_float4(0.f, 0.f, 0.f, 0.f);
                if ((unsigned)gr < (unsigned)WID)
                    a[b] = *(const float4*)(rowp);
            } else {
                a[b] = *(const float4*)(rowp);
            }
            rowp += WID;
        }

        const float4 av = a[r % 3];

        // Halo via warp shuffle: x[-2],x[-1] from lane-1; x[4],x[5] from lane+1.
        float slx = __shfl_up_sync(0xffffffffu, av.z, 1);
        float sly = __shfl_up_sync(0xffffffffu, av.w, 1);
        float shx = __shfl_down_sync(0xffffffffu, av.x, 1);
        float shy = __shfl_down_sync(0xffffffffu, av.y, 1);
        const float lx = has_l ? slx : 0.f;
        const float ly = has_l ? sly : 0.f;
        const float hx = has_h ? shx : 0.f;
        const float hy = has_h ? shy : 0.f;

        // Horizontal pair-sums for cols (c,c+1) and (c+2,c+3).
        // x[-2..5] = lx,ly, av.x,av.y,av.z,av.w, hx,hy
        u64 p01 = pk(av.x, av.y);
        u64 p23 = pk(av.z, av.w);
        u64 t1a = add2(pk(lx, ly), p23);                  // (x-2+x2, x-1+x3)
        u64 t2a = add2(pk(ly, av.x), pk(av.y, av.z));     // (x-1+x1, x0+x2)
        u64 t1b = add2(p01, pk(hx, hy));                  // (x0+x4,  x1+x5)
        u64 t2b = add2(pk(av.y, av.z), pk(av.w, hx));     // (x1+x3,  x2+x4)

        #pragma unroll
        for (int d = 0; d < 5; d++) {
            const int o = r - 4 + d;                      // receiving output row
            if (o < 0 || o >= STRIP) continue;            // constant-folded
            const int k = 2 - ((d < 2) ? (2 - d) : (d - 2));  // 0,1,2,1,0
            const int s = o % 5;
            if (d == 4) {                                 // first touch: assign
                acc0[s] = mul2(wp[k * 3 + 0], t1a);
                acc1[s] = mul2(wp[k * 3 + 0], t1b);
            } else {
                fma2(acc0[s], wp[k * 3 + 0], t1a);
                fma2(acc1[s], wp[k * 3 + 0], t1b);
            }
            fma2(acc0[s], wp[k * 3 + 1], t2a);
            fma2(acc0[s], wp[k * 3 + 2], p01);
            fma2(acc1[s], wp[k * 3 + 1], t2b);
            fma2(acc1[s], wp[k * 3 + 2], p23);
        }

        const int o = r - 4;                              // row completed now
        if (o >= 0) {                                     // constant-folded
            const int s = o % 5;
            float2 lo = unpk(acc0[s]);
            float2 hi = unpk(acc1[s]);
            __stcs((float4*)outp, make_float4(lo.x, lo.y, hi.x, hi.y));
            outp += WID;
        }
    }
}

// Thread layout: lane = tid&31 -> 4 output cols (c=lane*4);
// strip = tid>>5 (0..7) -> 16 output rows. One image per 256-thread block.
// Grid = 4096 blocks. No shared memory.
__global__ void __launch_bounds__(256, 4)
blur_main_kernel(const float* __restrict__ x, float* __restrict__ out,
                 const float* __restrict__ logls) {
    const int tid   = threadIdx.x;
    const int lane  = tid & 31;
    const int strip = tid >> 5;
    const int img   = blockIdx.x;
    const int c     = lane * 4;
    const int row0  = strip * STRIP;

    // ---- Per-thread weight table (5 expf, overlapped with first prefetch) ----
    const float inv2ls = 0.5f * expf(-logls[0]);   // 1/(2*exp(logls))
    const float e1 = expf(-1.0f  * inv2ls);
    const float e2 = expf(-4.0f  * inv2ls);
    const float e4 = expf(-16.0f * inv2ls);
    const float e5 = expf(-25.0f * inv2ls);
    const float e8 = expf(-64.0f * inv2ls);
    const float inv = 1.0f / (1.0f + 4.0f * (e1 + e2 + e4 + e8) + 8.0f * e5);
    // wp[k*3+j]: k = row class (|dy|=2-k), j = col class (|dx|=2-j)
    u64 wp[9];
    wp[0] = pk1(e8 * inv); wp[1] = pk1(e5 * inv); wp[2] = pk1(e4 * inv);
    wp[3] = wp[1];         wp[4] = pk1(e2 * inv); wp[5] = pk1(e1 * inv);
    wp[6] = wp[2];         wp[7] = wp[5];         wp[8] = pk1(inv);

    const float* rowp = x + (size_t)img * (WID * WID) + (row0 - RAD) * WID + c;
    float*       outp = out + (size_t)img * (WID * WID) + row0 * WID + c;

    const bool has_l = (lane > 0);
    const bool has_h = (lane < 31);

    if (strip == 0 || strip == 7)
        blur_strip<true >(rowp, outp, wp, has_l, has_h, row0);
    else
        blur_strip<false>(rowp, outp, wp, has_l, has_h, row0);
}

extern "C" void kernel_launch(void* const* d_in, const int* in_sizes, int n_in,
                              void* d_out, int out_size) {
    const float* x     = (const float*)d_in[0];
    const float* logls = (const float*)d_in[1];
    float* out = (float*)d_out;

    blur_main_kernel<<<4096, 256>>>(x, out, logls);
}